// round 7
// baseline (speedup 1.0000x reference)
#include <cuda_runtime.h>
#include <cuda_fp16.h>
#include <cstdint>

#define NTHR  512
#define ET    128
#define XSTR  264     // halves (row stride; multiple of 8 for 16B STS)
#define W1STR 136
#define W2STR 96
#define HSTR  136
// byte offsets in dynamic smem
#define B_X0  0            // 67584
#define B_X1  67584        // 67584
#define B_W1  135168       // 69632
#define B_W2  204800       // 24576
#define B_DST 229376       // 2 * 128 * 4
#define SMEMB 230400

__device__ __forceinline__ uint32_t s2u(const void* p) {
    uint32_t a; asm("{ .reg .u64 t; cvta.to.shared.u64 t, %1; cvt.u32.u64 %0, t; }" : "=r"(a) : "l"(p)); return a;
}
__device__ __forceinline__ void ldsm4(uint32_t a, uint32_t& r0, uint32_t& r1, uint32_t& r2, uint32_t& r3) {
    asm volatile("ldmatrix.sync.aligned.m8n8.x4.shared.b16 {%0,%1,%2,%3}, [%4];"
                 : "=r"(r0), "=r"(r1), "=r"(r2), "=r"(r3) : "r"(a));
}
__device__ __forceinline__ void ldsm4t(uint32_t a, uint32_t& r0, uint32_t& r1, uint32_t& r2, uint32_t& r3) {
    asm volatile("ldmatrix.sync.aligned.m8n8.x4.trans.shared.b16 {%0,%1,%2,%3}, [%4];"
                 : "=r"(r0), "=r"(r1), "=r"(r2), "=r"(r3) : "r"(a));
}
__device__ __forceinline__ void ldsm2t(uint32_t a, uint32_t& r0, uint32_t& r1) {
    asm volatile("ldmatrix.sync.aligned.m8n8.x2.trans.shared.b16 {%0,%1}, [%2];"
                 : "=r"(r0), "=r"(r1) : "r"(a));
}
__device__ __forceinline__ void mma16816(float* c, const uint32_t* a, const uint32_t* b) {
    asm volatile("mma.sync.aligned.m16n8k16.row.col.f32.f16.f16.f32 "
                 "{%0,%1,%2,%3}, {%4,%5,%6,%7}, {%8,%9}, {%0,%1,%2,%3};"
                 : "+f"(c[0]), "+f"(c[1]), "+f"(c[2]), "+f"(c[3])
                 : "r"(a[0]), "r"(a[1]), "r"(a[2]), "r"(a[3]), "r"(b[0]), "r"(b[1]));
}
__device__ __forceinline__ void red4(float* p, float a, float b, float c, float d) {
    asm volatile("red.global.add.v4.f32 [%0], {%1,%2,%3,%4};"
                 :: "l"(p), "f"(a), "f"(b), "f"(c), "f"(d) : "memory");
}
// 8 fp32 -> 8 fp16, one 16B STS at half-index idx (idx multiple of 8)
__device__ __forceinline__ void wr8h(__half* px, int idx, const float* v) {
    uint4 u;
    uint32_t* w = (uint32_t*)&u;
    #pragma unroll
    for (int q = 0; q < 4; q++) {
        __half h0 = __float2half_rn(v[2*q]), h1 = __float2half_rn(v[2*q+1]);
        w[q] = (uint32_t)__half_as_ushort(h0) | ((uint32_t)__half_as_ushort(h1) << 16);
    }
    *(uint4*)(px + idx) = u;
}
// inverse-rotate one rep (8 values)
__device__ __forceinline__ void rot8(const float* p, const float4* rk, float* o) {
    #pragma unroll
    for (int k = 0; k < 4; k++) {
        float x0 = p[2*k], x1 = p[2*k+1];
        o[2*k]   = x0 * rk[k].x + x1 * rk[k].y;
        o[2*k+1] = x0 * rk[k].z + x1 * rk[k].w;
    }
}

__global__ __launch_bounds__(NTHR, 1)
void eq_main(const float* __restrict__ xs, const float* __restrict__ xr,
             const int* __restrict__ ei, const float* __restrict__ dist,
             const float* __restrict__ rot,
             const float* __restrict__ W1, const float* __restrict__ b1,
             const float* __restrict__ W2, const float* __restrict__ b2,
             float* __restrict__ outS, float* __restrict__ outR,
             int E, int n_tiles)
{
    extern __shared__ __align__(16) unsigned char dyn[];
    const uint32_t sb = s2u(dyn);
    __half* sW1 = (__half*)(dyn + B_W1);
    __half* sW2 = (__half*)(dyn + B_W2);
    int*   sDst = (int*)  (dyn + B_DST);

    const int tid = threadIdx.x, lane = tid & 31, wid = tid >> 5;
    const int mw = wid >> 2, nw = wid & 3;
    const int lr = lane & 15, lc = (lane >> 4) << 3;
    const int g  = lane >> 2, tc = (lane & 3) * 2;

    // ---- stage weights once (fp16) ----
    for (int i = tid; i < 256 * 128; i += NTHR) {
        int k = i >> 7, n = i & 127;
        sW1[k * W1STR + n] = __float2half_rn(W1[i]);
    }
    for (int i = tid; i < 128 * 96; i += NTHR) {
        int k = i / 96, n = i - k * 96;
        sW2[k * W2STR + n] = __float2half_rn(W2[i]);
    }

    // phase-A gather/rotate for tile `t` into buffer `buf`
    auto phaseA = [&](int t, int buf) {
        __half* X = (__half*)(dyn + (buf ? B_X1 : B_X0));
        const int eL = tid >> 2, s = tid & 3;
        const int base = t * ET;
        const int e  = base + eL;
        const int ec = (e < E) ? e : (E - 1);
        const int srcn = ei[ec], dstn = ei[E + ec];
        if (s == 0) sDst[buf * ET + eL] = dstn;
        float4 rk[4];
        #pragma unroll
        for (int k = 0; k < 4; k++) rk[k] = *(const float4*)(rot + (size_t)ec * 16 + k * 4);
        const int rb = eL * XSTR;
        float tmp[8];
        #pragma unroll
        for (int q = 0; q < 2; q++) *(float4*)(tmp + 4*q) = *(const float4*)(xs + (size_t)dstn * 32 + s * 8 + 4*q);
        wr8h(X, rb + s * 8, tmp);
        #pragma unroll
        for (int q = 0; q < 2; q++) *(float4*)(tmp + 4*q) = *(const float4*)(xs + (size_t)srcn * 32 + s * 8 + 4*q);
        wr8h(X, rb + 96 + s * 8, tmp);
        #pragma unroll
        for (int jj = 0; jj < 2; jj++) {
            const int j = 2 * s + jj;
            float in[8];
            *(float4*)(in)     = *(const float4*)(xr + (size_t)dstn * 64 + j * 8);
            *(float4*)(in + 4) = *(const float4*)(xr + (size_t)dstn * 64 + j * 8 + 4);
            rot8(in, rk, tmp);  wr8h(X, rb + 32 + j * 8, tmp);
            *(float4*)(in)     = *(const float4*)(xr + (size_t)srcn * 64 + j * 8);
            *(float4*)(in + 4) = *(const float4*)(xr + (size_t)srcn * 64 + j * 8 + 4);
            rot8(in, rk, tmp);  wr8h(X, rb + 128 + j * 8, tmp);
        }
        #pragma unroll
        for (int q = 0; q < 2; q++) *(float4*)(tmp + 4*q) = *(const float4*)(dist + (size_t)ec * 64 + s * 16 + 4*q);
        wr8h(X, rb + 192 + s * 16, tmp);
        #pragma unroll
        for (int q = 0; q < 2; q++) *(float4*)(tmp + 4*q) = *(const float4*)(dist + (size_t)ec * 64 + s * 16 + 8 + 4*q);
        wr8h(X, rb + 200 + s * 16, tmp);
    };

    const int t0 = blockIdx.x, gstride = gridDim.x;
    if (t0 < n_tiles) phaseA(t0, 0);
    __syncthreads();

    int cur = 0;
    for (int t = t0; t < n_tiles; t += gstride) {
        const int base = t * ET;
        const uint32_t xB = sb + (cur ? B_X1 : B_X0);
        const uint32_t w1B = sb + B_W1, w2B = sb + B_W2;

        // ================= GEMM1: 128 x 128 x 256 =================
        float acc[2][4][4] = {};
        #pragma unroll 2
        for (int ks = 0; ks < 16; ks++) {
            const int k0 = ks * 16;
            uint32_t b[4][2];
            ldsm4t(w1B + (uint32_t)(((k0 + lr) * W1STR + nw * 32 + lc) * 2),
                   b[0][0], b[0][1], b[1][0], b[1][1]);
            ldsm4t(w1B + (uint32_t)(((k0 + lr) * W1STR + nw * 32 + 16 + lc) * 2),
                   b[2][0], b[2][1], b[3][0], b[3][1]);
            uint32_t A[2][4];
            #pragma unroll
            for (int mi = 0; mi < 2; mi++)
                ldsm4(xB + (uint32_t)(((mw * 32 + mi * 16 + lr) * XSTR + k0 + lc) * 2),
                      A[mi][0], A[mi][1], A[mi][2], A[mi][3]);
            #pragma unroll
            for (int mi = 0; mi < 2; mi++)
                #pragma unroll
                for (int nt = 0; nt < 4; nt++)
                    mma16816(acc[mi][nt], A[mi], b[nt]);
        }

        // ---- prefetch next tile's X into the other buffer.
        // Safe vs this iter's G1 (reads `cur` buffer only) and vs the PREVIOUS
        // iter's G2 readers of buffer cur^1 (ordered by the loop-end barrier).
        if (t + gstride < n_tiles) phaseA(t + gstride, cur ^ 1);
        __syncthreads();   // S1: all G1 reads of X[cur] done; next X staged

        // ================= epilogue1: bias + silu -> H (overlays X[cur]) ==========
        {
            __half* sH = (__half*)(dyn + (cur ? B_X1 : B_X0));
            #pragma unroll
            for (int mi = 0; mi < 2; mi++) {
                const int r0 = mw * 32 + mi * 16 + g;
                #pragma unroll
                for (int ni = 0; ni < 4; ni++) {
                    const int c = nw * 32 + ni * 8 + tc;
                    float2 bb = *(const float2*)(b1 + c);
                    float v[4];
                    v[0] = acc[mi][ni][0] + bb.x;  v[1] = acc[mi][ni][1] + bb.y;
                    v[2] = acc[mi][ni][2] + bb.x;  v[3] = acc[mi][ni][3] + bb.y;
                    #pragma unroll
                    for (int q = 0; q < 4; q++) v[q] = v[q] / (1.f + __expf(-v[q]));
                    #pragma unroll
                    for (int rh = 0; rh < 2; rh++) {
                        const int r = r0 + rh * 8;
                        __half h0 = __float2half_rn(v[rh*2]), h1 = __float2half_rn(v[rh*2+1]);
                        *(uint32_t*)(sH + r * HSTR + c) =
                            (uint32_t)__half_as_ushort(h0) | ((uint32_t)__half_as_ushort(h1) << 16);
                    }
                }
            }
        }
        __syncthreads();   // S2: H visible to all warps

        // ================= GEMM2: 128 x 96 x 128 =================
        float acc2[2][3][4] = {};
        {
            const uint32_t hB = xB;   // H overlays X[cur]
            #pragma unroll 2
            for (int ks = 0; ks < 8; ks++) {
                const int k0 = ks * 16;
                uint32_t b[3][2];
                ldsm4t(w2B + (uint32_t)(((k0 + lr) * W2STR + nw * 24 + lc) * 2),
                       b[0][0], b[0][1], b[1][0], b[1][1]);
                ldsm2t(w2B + (uint32_t)(((k0 + lr) * W2STR + nw * 24 + 16) * 2),
                       b[2][0], b[2][1]);
                uint32_t A[2][4];
                #pragma unroll
                for (int mi = 0; mi < 2; mi++)
                    ldsm4(hB + (uint32_t)(((mw * 32 + mi * 16 + lr) * HSTR + k0 + lc) * 2),
                          A[mi][0], A[mi][1], A[mi][2], A[mi][3]);
                #pragma unroll
                for (int mi = 0; mi < 2; mi++)
                    #pragma unroll
                    for (int nt = 0; nt < 3; nt++)
                        mma16816(acc2[mi][nt], A[mi], b[nt]);
            }
        }

        // ================= epilogue2: bias + rotate + shfl-pair + red4 ============
        // Lanes l (even) and l+1 hold adjacent col pairs of the SAME row:
        // merge via shfl so even lanes issue one red4 covering 4 columns.
        #pragma unroll
        for (int mi = 0; mi < 2; mi++) {
            const int rr = mw * 32 + mi * 16 + g;
            #pragma unroll
            for (int rh = 0; rh < 2; rh++) {
                const int r  = rr + rh * 8;
                const int e  = base + r;
                const int ec = (e < E) ? e : (E - 1);
                const int nidx = sDst[cur * ET + r];
                #pragma unroll
                for (int ni = 0; ni < 3; ni++) {
                    const int c = nw * 24 + ni * 8 + tc;
                    float2 bb = *(const float2*)(b2 + c);
                    float m0 = acc2[mi][ni][rh*2]   + bb.x;
                    float m1 = acc2[mi][ni][rh*2+1] + bb.y;
                    float v0, v1;
                    if (c < 32) { v0 = m0; v1 = m1; }
                    else {
                        const int p = (c - 32) >> 1;
                        const int k = p & 3;
                        float4 R = *(const float4*)(rot + (size_t)ec * 16 + k * 4);
                        v0 = m0 * R.x + m1 * R.z;
                        v1 = m0 * R.y + m1 * R.w;
                    }
                    float w0 = __shfl_down_sync(0xFFFFFFFF, v0, 1);
                    float w1 = __shfl_down_sync(0xFFFFFFFF, v1, 1);
                    if (((lane & 1) == 0) && e < E) {
                        if (c < 32) red4(outS + (size_t)nidx * 32 + c, v0, v1, w0, w1);
                        else        red4(outR + (size_t)nidx * 64 + (c - 32), v0, v1, w0, w1);
                    }
                }
            }
        }
        __syncthreads();   // S0: protect buffer cur^1 (G2/epi2 readers done)
                           // before next iteration's phaseA overwrites it
        cur ^= 1;
    }
}

extern "C" void kernel_launch(void* const* d_in, const int* in_sizes, int n_in,
                              void* d_out, int out_size)
{
    const float* xs   = (const float*)d_in[0];
    const float* xr   = (const float*)d_in[1];
    const int*   ei   = (const int*)  d_in[2];
    const float* dist = (const float*)d_in[3];
    const float* rot  = (const float*)d_in[4];
    const float* W1   = (const float*)d_in[5];
    const float* b1   = (const float*)d_in[6];
    const float* W2   = (const float*)d_in[7];
    const float* b2   = (const float*)d_in[8];

    const int N = in_sizes[0] / 32;
    const int E = in_sizes[2] / 2;
    const int n_tiles = (E + ET - 1) / ET;

    float* outS = (float*)d_out;
    float* outR = outS + (size_t)N * 32;

    cudaMemsetAsync(d_out, 0, (size_t)out_size * sizeof(float), 0);
    cudaFuncSetAttribute(eq_main, cudaFuncAttributeMaxDynamicSharedMemorySize, SMEMB);
    int grid = n_tiles < 148 ? n_tiles : 148;
    eq_main<<<grid, NTHR, SMEMB>>>(xs, xr, ei, dist, rot, W1, b1, W2, b2,
                                   outS, outR, E, n_tiles);
}

// round 8
// speedup vs baseline: 1.0569x; 1.0569x over previous
#include <cuda_runtime.h>
#include <cuda_fp16.h>
#include <cstdint>

#define NTHR  640     // 512 consumer + 128 producer
#define NCONS 512
#define ET    128
#define XSTR  264     // halves
#define W1STR 136
#define W2STR 96
#define HSTR  136
// byte offsets in dynamic smem
#define B_X0  0            // 67584
#define B_X1  67584        // 67584
#define B_W1  135168       // 69632
#define B_W2  204800       // 24576
#define B_DST 229376       // 2 * 128 * 4
#define SMEMB 230400

// named barrier ids: FULL0=1 FULL1=2 EMPTY0=3 EMPTY1=4 C1=5 C2=6
#define BAR_SYNC(id, cnt)   asm volatile("bar.sync %0, %1;"   :: "r"(id), "r"(cnt) : "memory")
#define BAR_ARRIVE(id, cnt) asm volatile("bar.arrive %0, %1;" :: "r"(id), "r"(cnt) : "memory")

__device__ __forceinline__ uint32_t s2u(const void* p) {
    uint32_t a; asm("{ .reg .u64 t; cvta.to.shared.u64 t, %1; cvt.u32.u64 %0, t; }" : "=r"(a) : "l"(p)); return a;
}
__device__ __forceinline__ void ldsm4(uint32_t a, uint32_t& r0, uint32_t& r1, uint32_t& r2, uint32_t& r3) {
    asm volatile("ldmatrix.sync.aligned.m8n8.x4.shared.b16 {%0,%1,%2,%3}, [%4];"
                 : "=r"(r0), "=r"(r1), "=r"(r2), "=r"(r3) : "r"(a));
}
__device__ __forceinline__ void ldsm4t(uint32_t a, uint32_t& r0, uint32_t& r1, uint32_t& r2, uint32_t& r3) {
    asm volatile("ldmatrix.sync.aligned.m8n8.x4.trans.shared.b16 {%0,%1,%2,%3}, [%4];"
                 : "=r"(r0), "=r"(r1), "=r"(r2), "=r"(r3) : "r"(a));
}
__device__ __forceinline__ void ldsm2t(uint32_t a, uint32_t& r0, uint32_t& r1) {
    asm volatile("ldmatrix.sync.aligned.m8n8.x2.trans.shared.b16 {%0,%1}, [%2];"
                 : "=r"(r0), "=r"(r1) : "r"(a));
}
__device__ __forceinline__ void mma16816(float* c, const uint32_t* a, const uint32_t* b) {
    asm volatile("mma.sync.aligned.m16n8k16.row.col.f32.f16.f16.f32 "
                 "{%0,%1,%2,%3}, {%4,%5,%6,%7}, {%8,%9}, {%0,%1,%2,%3};"
                 : "+f"(c[0]), "+f"(c[1]), "+f"(c[2]), "+f"(c[3])
                 : "r"(a[0]), "r"(a[1]), "r"(a[2]), "r"(a[3]), "r"(b[0]), "r"(b[1]));
}
__device__ __forceinline__ void red2(float* p, float a, float b) {
    asm volatile("red.global.add.v2.f32 [%0], {%1,%2};" :: "l"(p), "f"(a), "f"(b) : "memory");
}
// 8 fp32 -> 8 fp16, one 16B STS
__device__ __forceinline__ void wr8h(__half* px, int idx, const float* v) {
    uint4 u;
    uint32_t* w = (uint32_t*)&u;
    #pragma unroll
    for (int q = 0; q < 4; q++) {
        __half h0 = __float2half_rn(v[2*q]), h1 = __float2half_rn(v[2*q+1]);
        w[q] = (uint32_t)__half_as_ushort(h0) | ((uint32_t)__half_as_ushort(h1) << 16);
    }
    *(uint4*)(px + idx) = u;
}
// inverse-rotate one rep (8 values)
__device__ __forceinline__ void rot8(const float* p, const float4* rk, float* o) {
    #pragma unroll
    for (int k = 0; k < 4; k++) {
        float x0 = p[2*k], x1 = p[2*k+1];
        o[2*k]   = x0 * rk[k].x + x1 * rk[k].y;
        o[2*k+1] = x0 * rk[k].z + x1 * rk[k].w;
    }
}

__global__ __launch_bounds__(NTHR, 1)
void eq_main(const float* __restrict__ xs, const float* __restrict__ xr,
             const int* __restrict__ ei, const float* __restrict__ dist,
             const float* __restrict__ rot,
             const float* __restrict__ W1, const float* __restrict__ b1,
             const float* __restrict__ W2, const float* __restrict__ b2,
             float* __restrict__ outS, float* __restrict__ outR,
             int E, int n_tiles)
{
    extern __shared__ __align__(16) unsigned char dyn[];
    const uint32_t sb = s2u(dyn);
    __half* sW1 = (__half*)(dyn + B_W1);
    __half* sW2 = (__half*)(dyn + B_W2);
    int*   sDst = (int*)  (dyn + B_DST);

    const int tid = threadIdx.x, lane = tid & 31, wid = tid >> 5;

    // ---- stage weights once (all threads) ----
    for (int i = tid; i < 256 * 128; i += NTHR) {
        int k = i >> 7, n = i & 127;
        sW1[k * W1STR + n] = __float2half_rn(W1[i]);
    }
    for (int i = tid; i < 128 * 96; i += NTHR) {
        int k = i / 96, n = i - k * 96;
        sW2[k * W2STR + n] = __float2half_rn(W2[i]);
    }
    __syncthreads();

    const int t0 = blockIdx.x, gstride = gridDim.x;

    if (wid >= 16) {
        // ================= PRODUCER: 4 warps, 1 thread per edge =================
        const int pe = tid - NCONS;      // 0..127
        int i = 0;
        for (int t = t0; t < n_tiles; t += gstride, i++) {
            const int buf = i & 1;
            if (i >= 2) BAR_SYNC(3 + buf, NTHR);        // wait EMPTY[buf]
            __half* X = (__half*)(dyn + (buf ? B_X1 : B_X0));
            const int base = t * ET;
            const int e  = base + pe;
            const int ec = (e < E) ? e : (E - 1);
            const int srcn = ei[ec], dstn = ei[E + ec];
            sDst[buf * ET + pe] = dstn;
            float4 rk[4];
            #pragma unroll
            for (int k = 0; k < 4; k++) rk[k] = *(const float4*)(rot + (size_t)ec * 16 + k * 4);
            const int rb = pe * XSTR;
            float tmp[8], in[8];
            // x_scalar dst -> cols 0..31
            #pragma unroll
            for (int q = 0; q < 4; q++) {
                *(float4*)(tmp)     = *(const float4*)(xs + (size_t)dstn * 32 + q * 8);
                *(float4*)(tmp + 4) = *(const float4*)(xs + (size_t)dstn * 32 + q * 8 + 4);
                wr8h(X, rb + q * 8, tmp);
            }
            // x_rot dst rotated -> cols 32..95
            #pragma unroll
            for (int j = 0; j < 8; j++) {
                *(float4*)(in)     = *(const float4*)(xr + (size_t)dstn * 64 + j * 8);
                *(float4*)(in + 4) = *(const float4*)(xr + (size_t)dstn * 64 + j * 8 + 4);
                rot8(in, rk, tmp);
                wr8h(X, rb + 32 + j * 8, tmp);
            }
            // x_scalar src -> cols 96..127
            #pragma unroll
            for (int q = 0; q < 4; q++) {
                *(float4*)(tmp)     = *(const float4*)(xs + (size_t)srcn * 32 + q * 8);
                *(float4*)(tmp + 4) = *(const float4*)(xs + (size_t)srcn * 32 + q * 8 + 4);
                wr8h(X, rb + 96 + q * 8, tmp);
            }
            // x_rot src rotated -> cols 128..191
            #pragma unroll
            for (int j = 0; j < 8; j++) {
                *(float4*)(in)     = *(const float4*)(xr + (size_t)srcn * 64 + j * 8);
                *(float4*)(in + 4) = *(const float4*)(xr + (size_t)srcn * 64 + j * 8 + 4);
                rot8(in, rk, tmp);
                wr8h(X, rb + 128 + j * 8, tmp);
            }
            // distance embedding -> cols 192..255
            #pragma unroll
            for (int q = 0; q < 8; q++) {
                *(float4*)(tmp)     = *(const float4*)(dist + (size_t)ec * 64 + q * 8);
                *(float4*)(tmp + 4) = *(const float4*)(dist + (size_t)ec * 64 + q * 8 + 4);
                wr8h(X, rb + 192 + q * 8, tmp);
            }
            BAR_ARRIVE(1 + buf, NTHR);                  // signal FULL[buf]
        }
    } else {
        // ================= CONSUMER: 16 warps =================
        const int mw = wid >> 2, nw = wid & 3;
        const int lr = lane & 15, lc = (lane >> 4) << 3;
        const int g  = lane >> 2, tc = (lane & 3) * 2;
        const uint32_t w1B = sb + B_W1, w2B = sb + B_W2;

        int i = 0;
        for (int t = t0; t < n_tiles; t += gstride, i++) {
            const int buf = i & 1;
            const int base = t * ET;
            const uint32_t xB = sb + (buf ? B_X1 : B_X0);

            BAR_SYNC(1 + buf, NTHR);                    // wait FULL[buf]

            // ---------- GEMM1: 128 x 128 x 256 ----------
            float acc[2][4][4] = {};
            #pragma unroll 2
            for (int ks = 0; ks < 16; ks++) {
                const int k0 = ks * 16;
                uint32_t b[4][2];
                ldsm4t(w1B + (uint32_t)(((k0 + lr) * W1STR + nw * 32 + lc) * 2),
                       b[0][0], b[0][1], b[1][0], b[1][1]);
                ldsm4t(w1B + (uint32_t)(((k0 + lr) * W1STR + nw * 32 + 16 + lc) * 2),
                       b[2][0], b[2][1], b[3][0], b[3][1]);
                uint32_t A[2][4];
                #pragma unroll
                for (int mi = 0; mi < 2; mi++)
                    ldsm4(xB + (uint32_t)(((mw * 32 + mi * 16 + lr) * XSTR + k0 + lc) * 2),
                          A[mi][0], A[mi][1], A[mi][2], A[mi][3]);
                #pragma unroll
                for (int mi = 0; mi < 2; mi++)
                    #pragma unroll
                    for (int nt = 0; nt < 4; nt++)
                        mma16816(acc[mi][nt], A[mi], b[nt]);
            }
            BAR_SYNC(5, NCONS);                         // G1 reads of X[buf] done

            // ---------- epilogue1: bias + silu -> H (overlays X[buf]) ----------
            {
                __half* sH = (__half*)(dyn + (buf ? B_X1 : B_X0));
                #pragma unroll
                for (int mi = 0; mi < 2; mi++) {
                    const int r0 = mw * 32 + mi * 16 + g;
                    #pragma unroll
                    for (int ni = 0; ni < 4; ni++) {
                        const int c = nw * 32 + ni * 8 + tc;
                        float2 bb = *(const float2*)(b1 + c);
                        float v[4];
                        v[0] = acc[mi][ni][0] + bb.x;  v[1] = acc[mi][ni][1] + bb.y;
                        v[2] = acc[mi][ni][2] + bb.x;  v[3] = acc[mi][ni][3] + bb.y;
                        #pragma unroll
                        for (int q = 0; q < 4; q++) v[q] = v[q] / (1.f + __expf(-v[q]));
                        #pragma unroll
                        for (int rh = 0; rh < 2; rh++) {
                            const int r = r0 + rh * 8;
                            __half h0 = __float2half_rn(v[rh*2]), h1 = __float2half_rn(v[rh*2+1]);
                            *(uint32_t*)(sH + r * HSTR + c) =
                                (uint32_t)__half_as_ushort(h0) | ((uint32_t)__half_as_ushort(h1) << 16);
                        }
                    }
                }
            }
            BAR_SYNC(6, NCONS);                         // H visible

            // ---------- GEMM2: 128 x 96 x 128 ----------
            float acc2[2][3][4] = {};
            #pragma unroll 2
            for (int ks = 0; ks < 8; ks++) {
                const int k0 = ks * 16;
                uint32_t b[3][2];
                ldsm4t(w2B + (uint32_t)(((k0 + lr) * W2STR + nw * 24 + lc) * 2),
                       b[0][0], b[0][1], b[1][0], b[1][1]);
                ldsm2t(w2B + (uint32_t)(((k0 + lr) * W2STR + nw * 24 + 16) * 2),
                       b[2][0], b[2][1]);
                uint32_t A[2][4];
                #pragma unroll
                for (int mi = 0; mi < 2; mi++)
                    ldsm4(xB + (uint32_t)(((mw * 32 + mi * 16 + lr) * HSTR + k0 + lc) * 2),
                          A[mi][0], A[mi][1], A[mi][2], A[mi][3]);
                #pragma unroll
                for (int mi = 0; mi < 2; mi++)
                    #pragma unroll
                    for (int nt = 0; nt < 3; nt++)
                        mma16816(acc2[mi][nt], A[mi], b[nt]);
            }

            // ---------- epilogue2: bias + forward rotate + scatter ----------
            #pragma unroll
            for (int mi = 0; mi < 2; mi++) {
                const int rr = mw * 32 + mi * 16 + g;
                #pragma unroll
                for (int rh = 0; rh < 2; rh++) {
                    const int r = rr + rh * 8;
                    const int e = base + r;
                    if (e < E) {
                        const int nidx = sDst[buf * ET + r];
                        #pragma unroll
                        for (int ni = 0; ni < 3; ni++) {
                            const int c = nw * 24 + ni * 8 + tc;
                            float2 bb = *(const float2*)(b2 + c);
                            float m0 = acc2[mi][ni][rh*2]   + bb.x;
                            float m1 = acc2[mi][ni][rh*2+1] + bb.y;
                            if (c < 32) {
                                red2(outS + (size_t)nidx * 32 + c, m0, m1);
                            } else {
                                const int p = (c - 32) >> 1;
                                const int k = p & 3;
                                float4 R = *(const float4*)(rot + (size_t)e * 16 + k * 4);
                                red2(outR + (size_t)nidx * 64 + 2 * p,
                                     m0 * R.x + m1 * R.z, m0 * R.y + m1 * R.w);
                            }
                        }
                    }
                }
            }
            BAR_ARRIVE(3 + buf, NTHR);                  // release EMPTY[buf]
        }
    }
}

extern "C" void kernel_launch(void* const* d_in, const int* in_sizes, int n_in,
                              void* d_out, int out_size)
{
    const float* xs   = (const float*)d_in[0];
    const float* xr   = (const float*)d_in[1];
    const int*   ei   = (const int*)  d_in[2];
    const float* dist = (const float*)d_in[3];
    const float* rot  = (const float*)d_in[4];
    const float* W1   = (const float*)d_in[5];
    const float* b1   = (const float*)d_in[6];
    const float* W2   = (const float*)d_in[7];
    const float* b2   = (const float*)d_in[8];

    const int N = in_sizes[0] / 32;
    const int E = in_sizes[2] / 2;
    const int n_tiles = (E + ET - 1) / ET;

    float* outS = (float*)d_out;
    float* outR = outS + (size_t)N * 32;

    cudaMemsetAsync(d_out, 0, (size_t)out_size * sizeof(float), 0);
    cudaFuncSetAttribute(eq_main, cudaFuncAttributeMaxDynamicSharedMemorySize, SMEMB);
    int grid = n_tiles < 148 ? n_tiles : 148;
    eq_main<<<grid, NTHR, SMEMB>>>(xs, xr, ei, dist, rot, W1, b1, W2, b2,
                                   outS, outR, E, n_tiles);
}